// round 6
// baseline (speedup 1.0000x reference)
#include <cuda_runtime.h>
#include <math.h>

#define BB 4
#define NN 1024
#define KNNK 16
#define N3 3072
#define NCOL 12288
#define CATC 352
#define EPSF 1e-12f

// ---- static scratch ----
__device__ __align__(16) float g_cat[BB * CATC * 3 * NN];  // [b][c][d][n]
__device__ __align__(16) float g_A [NCOL * 128];           // [cid][o], cid=b*3N+d*N+n
__device__ __align__(16) float g_Bm[NCOL * 128];
__device__ __align__(16) float g_Ad[NCOL * 128];
__device__ __align__(16) float g_Bd[NCOL * 128];
__device__ __align__(16) float g_U [NCOL * 128];
__device__ __align__(16) float g_Dc[NCOL];
__device__ __align__(16) float g_Wp[128 * 512];
__device__ __align__(16) float g_ycc[BB * 128 * 3 * NN];
__device__ __align__(16) float g_y[BB * 128 * 3];
__device__ int g_idx[BB * NN * KNNK];

// ---- KNN: bit-careful fp32 d2 = (sq_n + sq_m) - 2*dot ----
// sq: no-FMA ((x*x + y*y) + z*z); dot: ascending FMA chain (cublas/Eigen K-loop)
__global__ void knn_k(const float* __restrict__ x) {
    __shared__ float ssq[NN];
    __shared__ float sd[NN];
    __shared__ float rv[8];
    __shared__ int   ri[8];
    int bn = blockIdx.x;
    int b = bn >> 10, n = bn & (NN - 1);
    int tid = threadIdx.x;
    const float* xb = x + (size_t)b * N3;
    for (int m = tid; m < NN; m += 256) {
        float qx = xb[m], qy = xb[NN + m], qz = xb[2*NN + m];
        ssq[m] = __fadd_rn(__fadd_rn(__fmul_rn(qx, qx), __fmul_rn(qy, qy)),
                           __fmul_rn(qz, qz));
    }
    __syncthreads();
    float px = xb[n], py = xb[NN + n], pz = xb[2*NN + n];
    float sqn = ssq[n];
    for (int m = tid; m < NN; m += 256) {
        float qx = xb[m], qy = xb[NN + m], qz = xb[2*NN + m];
        float dot = __fmaf_rn(pz, qz, __fmaf_rn(py, qy, __fmul_rn(px, qx)));
        sd[m] = __fsub_rn(__fadd_rn(sqn, ssq[m]), __fmul_rn(2.0f, dot));
    }
    __syncthreads();
    for (int k = 0; k < KNNK; k++) {
        float bv = INFINITY; int bi = 0x7fffffff;
        for (int m = tid; m < NN; m += 256) {
            float v = sd[m];
            if (v < bv || (v == bv && m < bi)) { bv = v; bi = m; }
        }
        for (int off = 16; off > 0; off >>= 1) {
            float ov = __shfl_down_sync(0xffffffffu, bv, off);
            int   oi = __shfl_down_sync(0xffffffffu, bi, off);
            if (ov < bv || (ov == bv && oi < bi)) { bv = ov; bi = oi; }
        }
        if ((tid & 31) == 0) { rv[tid >> 5] = bv; ri[tid >> 5] = bi; }
        __syncthreads();
        if (tid == 0) {
            float fv = rv[0]; int fi = ri[0];
            for (int w = 1; w < 8; w++)
                if (rv[w] < fv || (rv[w] == fv && ri[w] < fi)) { fv = rv[w]; fi = ri[w]; }
            g_idx[bn * KNNK + k] = fi;
            sd[fi] = INFINITY;
        }
        __syncthreads();
    }
}

// ---- g_Wp = Wd @ W (fp32) ----
__global__ void wcomb_k(const float* __restrict__ Wd, int Cm,
                        const float* __restrict__ W, int wcols) {
    int o = blockIdx.x;
    int j = threadIdx.x;
    if (j >= wcols) return;
    float s = 0.f;
    for (int m = 0; m < Cm; m++) s += Wd[o * Cm + m] * W[m * wcols + j];
    g_Wp[o * wcols + j] = s;
}

// ---- skinny GEMM over 12288 columns (fp32) ----
__device__ __forceinline__ float* out_sel(int s) {
    switch (s) {
        case 0: return g_A;
        case 1: return g_Bm;
        case 2: return g_Ad;
        case 3: return g_Bd;
        default: return g_U;
    }
}
__global__ void gemm_k(const float* __restrict__ Wparam, int wsel, int ldw, int mode,
                       const float* __restrict__ xin, int finoff,
                       int Cin, size_t bstride, int outsel, int Cout) {
    extern __shared__ float ws[];
    const float* W = wsel ? g_Wp : Wparam;
    const int R = 8;
    int o0 = blockIdx.y * R;
    for (int t = threadIdx.x; t < R * Cin; t += blockDim.x) {
        int i = t / Cin, c = t - i * Cin;
        float w = W[(o0 + i) * ldw + c];
        if (mode) w = W[(o0 + i) * ldw + Cin + c] - w;
        ws[t] = w;
    }
    __syncthreads();
    const float* FIN = xin ? xin : (g_cat + finoff);
    float* OUT = out_sel(outsel);
    int cid = (blockIdx.x * blockDim.x + threadIdx.x) * 4;
    int b = cid / N3;
    int dn = cid - b * N3;
    const float* fin = FIN + (size_t)b * bstride + dn;
    float acc[8][4];
#pragma unroll
    for (int i = 0; i < 8; i++) { acc[i][0]=0.f; acc[i][1]=0.f; acc[i][2]=0.f; acc[i][3]=0.f; }
    for (int c = 0; c < Cin; c++) {
        float4 f = *reinterpret_cast<const float4*>(fin + (size_t)c * N3);
#pragma unroll
        for (int i = 0; i < 8; i++) {
            float w = ws[i * Cin + c];
            acc[i][0] += w * f.x; acc[i][1] += w * f.y;
            acc[i][2] += w * f.z; acc[i][3] += w * f.w;
        }
    }
#pragma unroll
    for (int j = 0; j < 4; j++) {
        float* op = OUT + (size_t)(cid + j) * Cout + o0;
#pragma unroll
        for (int i = 0; i < 8; i++) op[i] = acc[i][j];
    }
}

// ---- edge: gather + vec_act + mean over K ----
__global__ void edge_k(int Cout, int coff) {
    int bn = blockIdx.x;
    int b = bn >> 10, n = bn & (NN - 1);
    int c = threadIdx.x;
    const int* ip = g_idx + bn * KNNK;
    int bn0 = b * N3 + n;
    size_t sN = (size_t)NN * Cout;
    size_t pn = (size_t)bn0 * Cout + c;
    float bm0 = g_Bm[pn], bm1 = g_Bm[pn + sN], bm2 = g_Bm[pn + 2*sN];
    float bd0 = g_Bd[pn], bd1 = g_Bd[pn + sN], bd2 = g_Bd[pn + 2*sN];
    float a0 = 0.f, a1 = 0.f, a2 = 0.f;
    for (int k = 0; k < KNNK; k++) {
        int j = ip[k];
        size_t pj = (size_t)(b * N3 + j) * Cout + c;
        float y0 = g_A[pj]        + bm0;
        float y1 = g_A[pj + sN]   + bm1;
        float y2 = g_A[pj + 2*sN] + bm2;
        float d0 = g_Ad[pj]        + bd0;
        float d1 = g_Ad[pj + sN]   + bd1;
        float d2 = g_Ad[pj + 2*sN] + bd2;
        float dm = fmaxf(sqrtf(d0*d0 + d1*d1 + d2*d2), EPSF);
        float k0 = d0/dm, k1 = d1/dm, k2 = d2/dm;
        float dot = y0*k0 + y1*k1 + y2*k2;
        float coef = (dot < 0.f) ? (-0.8f * dot) : 0.f;
        a0 += y0 + coef*k0; a1 += y1 + coef*k1; a2 += y2 + coef*k2;
    }
    const float s = 1.0f / 16.0f;
    size_t ob = ((size_t)(b * CATC + coff + c) * 3) * NN + n;
    g_cat[ob] = a0 * s; g_cat[ob + NN] = a1 * s; g_cat[ob + 2*NN] = a2 * s;
}

// ---- g_Dc[cid] = ccD . g_U[cid,:] ----
__global__ void dc_k(const float* __restrict__ ccD) {
    int cid = blockIdx.x * 256 + threadIdx.x;
    const float* u = g_U + (size_t)cid * 128;
    float s = 0.f;
    for (int o = 0; o < 128; o++) s += ccD[o] * u[o];
    g_Dc[cid] = s;
}

// ---- cc vec_act with shared 1-channel direction ----
__global__ void ccact_k() {
    int bn = blockIdx.x;
    int b = bn >> 10, n = bn & (NN - 1);
    int c = threadIdx.x;
    int bn0 = b * N3 + n;
    float d0 = g_Dc[bn0], d1 = g_Dc[bn0 + NN], d2 = g_Dc[bn0 + 2*NN];
    float dm = fmaxf(sqrtf(d0*d0 + d1*d1 + d2*d2), EPSF);
    float k0 = d0/dm, k1 = d1/dm, k2 = d2/dm;
    size_t sN = (size_t)NN * 128;
    size_t p = (size_t)bn0 * 128 + c;
    float u0 = g_U[p], u1 = g_U[p + sN], u2 = g_U[p + 2*sN];
    float dot = u0*k0 + u1*k1 + u2*k2;
    float coef = (dot < 0.f) ? (-0.8f * dot) : 0.f;
    size_t ob = ((size_t)(b * 128 + c) * 3) * NN + n;
    g_ycc[ob] = u0 + coef*k0; g_ycc[ob + NN] = u1 + coef*k1; g_ycc[ob + 2*NN] = u2 + coef*k2;
}

// ---- mean over N ----
__global__ void reduce_k() {
    __shared__ float s[256];
    const float* p = g_ycc + (size_t)blockIdx.x * NN;
    int t = threadIdx.x;
    s[t] = p[t] + p[t + 256] + p[t + 512] + p[t + 768];
    __syncthreads();
    for (int off = 128; off > 0; off >>= 1) {
        if (t < off) s[t] += s[t + off];
        __syncthreads();
    }
    if (t == 0) g_y[blockIdx.x] = s[0] * (1.0f / NN);
}

// ---- head helpers (fp32) ----
__device__ __forceinline__ float bsum128(float v, float* s) {
    int t = threadIdx.x;
    s[t] = v; __syncthreads();
    for (int off = 64; off > 0; off >>= 1) {
        if (t < off) s[t] += s[t + off];
        __syncthreads();
    }
    float r = s[0]; __syncthreads();
    return r;
}
__device__ __forceinline__ void gemm3(float (*dst)[3], const float* W,
                                      const float (*src)[3], int Cout, int Cin, int c) {
    if (c < Cout) {
        float a0 = 0.f, a1 = 0.f, a2 = 0.f;
        for (int m = 0; m < Cin; m++) {
            float w = W[c * Cin + m];
            a0 += w * src[m][0]; a1 += w * src[m][1]; a2 += w * src[m][2];
        }
        dst[c][0] = a0; dst[c][1] = a1; dst[c][2] = a2;
    }
}
__device__ __forceinline__ void act_sq(float (*dst)[3], const float (*x)[3],
                                       const float* Wd, int C, int c) {
    if (c < C) {
        float d0 = 0.f, d1 = 0.f, d2 = 0.f;
        for (int m = 0; m < C; m++) {
            float w = Wd[c * C + m];
            d0 += w * x[m][0]; d1 += w * x[m][1]; d2 += w * x[m][2];
        }
        float dm = fmaxf(sqrtf(d0*d0 + d1*d1 + d2*d2), EPSF);
        float k0 = d0/dm, k1 = d1/dm, k2 = d2/dm;
        float dot = x[c][0]*k0 + x[c][1]*k1 + x[c][2]*k2;
        float coef = (dot < 0.f) ? (-0.8f * dot) : 0.f;
        dst[c][0] = x[c][0] + coef*k0;
        dst[c][1] = x[c][1] + coef*k1;
        dst[c][2] = x[c][2] + coef*k2;
    }
}

__global__ void head_k(const float* __restrict__ fcO,
                       const float* __restrict__ rbDin, const float* __restrict__ rbW0,
                       const float* __restrict__ rbDh,  const float* __restrict__ rbW1,
                       const float* __restrict__ rbWs,
                       const float* __restrict__ m0W, const float* __restrict__ m0D,
                       const float* __restrict__ m1W, const float* __restrict__ m1D,
                       const float* __restrict__ l0W, const float* __restrict__ l0D,
                       const float* __restrict__ l1W, const float* __restrict__ l1D,
                       const float* __restrict__ fimW, const float* __restrict__ filW,
                       float* __restrict__ out) {
    int b = blockIdx.x, c = threadIdx.x;
    __shared__ float sy[128][3], syn[128][3], t0[128][3], t1[128][3], t2[128][3];
    __shared__ float sred[128];
    __shared__ float sR[9];

    float y0 = g_y[(b*128 + c)*3 + 0];
    float y1 = g_y[(b*128 + c)*3 + 1];
    float y2 = g_y[(b*128 + c)*3 + 2];
    sy[c][0] = y0; sy[c][1] = y1; sy[c][2] = y2;
    float nc = sqrtf(y0*y0 + y1*y1 + y2*y2);
    __syncthreads();

    // scale
    float ss = bsum128(nc + EPSF, sred);
    if (c == 0) out[1060 + b] = ss * (1.0f / 128.0f) * 640.0f;

    // cevn(y)
    float S = bsum128(nc * nc, sred);
    float nn = nc / fmaxf(sqrtf(S), EPSF);
    float invn = fmaxf(nc, EPSF);
    syn[c][0] = y0/invn*nn; syn[c][1] = y1/invn*nn; syn[c][2] = y2/invn*nn;
    __syncthreads();

    // R[d][o] = sum_c fcO[o][c]*syn[c][d]
    for (int o = 0; o < 3; o++) {
        float wo = fcO[o * 128 + c];
        for (int d = 0; d < 3; d++) {
            float r = bsum128(wo * syn[c][d], sred);
            if (c == 0) sR[d*3 + o] = r;
        }
    }
    __syncthreads();

    // polar (det-scaled Newton); so3_out = transpose(Q)
    if (c == 0) {
        float X[9], Cf[9];
        float fn = 0.f;
        for (int i = 0; i < 9; i++) { X[i] = sR[i]; fn += X[i]*X[i]; }
        fn = sqrtf(fn); if (fn < 1e-20f) fn = 1e-20f;
        for (int i = 0; i < 9; i++) X[i] /= fn;
        for (int it = 0; it < 25; it++) {
            Cf[0] =  (X[4]*X[8] - X[5]*X[7]);
            Cf[1] = -(X[3]*X[8] - X[5]*X[6]);
            Cf[2] =  (X[3]*X[7] - X[4]*X[6]);
            Cf[3] = -(X[1]*X[8] - X[2]*X[7]);
            Cf[4] =  (X[0]*X[8] - X[2]*X[6]);
            Cf[5] = -(X[0]*X[7] - X[1]*X[6]);
            Cf[6] =  (X[1]*X[5] - X[2]*X[4]);
            Cf[7] = -(X[0]*X[5] - X[2]*X[3]);
            Cf[8] =  (X[0]*X[4] - X[1]*X[3]);
            float det = X[0]*Cf[0] + X[1]*Cf[1] + X[2]*Cf[2];
            float ad = fabsf(det);
            if (ad < 1e-30f) break;
            float z = 1.0f / cbrtf(ad);
            float invd = 1.0f / det;
            for (int i = 0; i < 9; i++)
                X[i] = 0.5f * (z * X[i] + (Cf[i] * invd) / z);
        }
        for (int i = 0; i < 3; i++)
            for (int j = 0; j < 3; j++)
                out[1024 + b*9 + i*3 + j] = X[j*3 + i];
    }

    // residual block: center
    act_sq(t0, sy, rbDin, 128, c);
    __syncthreads();
    gemm3(t1, rbW0, t0, 64, 128, c);
    __syncthreads();
    act_sq(t2, t1, rbDh, 64, c);
    __syncthreads();
    if (c < 3) {
        float dx = 0.f;
        for (int m = 0; m < 64; m++) dx += rbW1[m] * t2[m][c];
        float wsv = 0.f;
        for (int m = 0; m < 128; m++) wsv += rbWs[m] * sy[m][c];
        out[1064 + b*3 + c] = (wsv + dx) * 640.0f;
    }
    __syncthreads();

    // mean branch
    gemm3(t0, m0W, syn, 128, 128, c); __syncthreads();
    act_sq(t1, t0, m0D, 128, c);      __syncthreads();
    gemm3(t0, m1W, t1, 128, 128, c);  __syncthreads();
    act_sq(t2, t0, m1D, 128, c);      __syncthreads();
    gemm3(t0, fimW, t2, 128, 128, c); __syncthreads();
    out[b*128 + c] = t2[c][0]*t0[c][0] + t2[c][1]*t0[c][1] + t2[c][2]*t0[c][2];
    __syncthreads();

    // logvar branch
    gemm3(t0, l0W, syn, 128, 128, c); __syncthreads();
    act_sq(t1, t0, l0D, 128, c);      __syncthreads();
    gemm3(t0, l1W, t1, 128, 128, c);  __syncthreads();
    act_sq(t2, t0, l1D, 128, c);      __syncthreads();
    gemm3(t0, filW, t2, 128, 128, c); __syncthreads();
    out[512 + b*128 + c] = t2[c][0]*t0[c][0] + t2[c][1]*t0[c][1] + t2[c][2]*t0[c][2];
}

// ---- host-side layer driver ----
static void run_layer(const float* W, const float* Wd, int Cin, int Cout,
                      const float* xin, int finoff, size_t bstride, int coff) {
    int wcols = 2 * Cin;
    wcomb_k<<<Cout, wcols>>>(Wd, Cout, W, wcols);
    dim3 g(24, Cout / 8);
    size_t sm = (size_t)8 * Cin * sizeof(float);
    gemm_k<<<g, 128, sm>>>(W, 0, wcols, 0, xin, finoff, Cin, bstride, 0, Cout);
    gemm_k<<<g, 128, sm>>>(W, 0, wcols, 1, xin, finoff, Cin, bstride, 1, Cout);
    gemm_k<<<g, 128, sm>>>(W, 1, wcols, 0, xin, finoff, Cin, bstride, 2, Cout);
    gemm_k<<<g, 128, sm>>>(W, 1, wcols, 1, xin, finoff, Cin, bstride, 3, Cout);
    edge_k<<<BB * NN, Cout>>>(Cout, coff);
}

extern "C" void kernel_launch(void* const* d_in, const int* in_sizes, int n_in,
                              void* d_out, int out_size) {
    const float* x    = (const float*)d_in[0];
    const float* c1W  = (const float*)d_in[2];
    const float* c1D  = (const float*)d_in[3];
    const float* c2W  = (const float*)d_in[4];
    const float* c2D  = (const float*)d_in[5];
    const float* c3W  = (const float*)d_in[6];
    const float* c3D  = (const float*)d_in[7];
    const float* c4W  = (const float*)d_in[8];
    const float* c4D  = (const float*)d_in[9];
    const float* ccW  = (const float*)d_in[10];
    const float* ccD  = (const float*)d_in[11];
    const float* fcO  = (const float*)d_in[12];
    const float* m0W  = (const float*)d_in[13];
    const float* m0D  = (const float*)d_in[14];
    const float* m1W  = (const float*)d_in[15];
    const float* m1D  = (const float*)d_in[16];
    const float* l0W  = (const float*)d_in[17];
    const float* l0D  = (const float*)d_in[18];
    const float* l1W  = (const float*)d_in[19];
    const float* l1D  = (const float*)d_in[20];
    const float* fimW = (const float*)d_in[21];
    const float* filW = (const float*)d_in[22];
    const float* rbDin= (const float*)d_in[23];
    const float* rbW0 = (const float*)d_in[24];
    const float* rbDh = (const float*)d_in[25];
    const float* rbW1 = (const float*)d_in[26];
    const float* rbWs = (const float*)d_in[27];
    float* out = (float*)d_out;

    knn_k<<<BB * NN, 256>>>(x);

    size_t catbs = (size_t)CATC * N3;
    run_layer(c1W, c1D, 1,   32,  x,       0,        (size_t)N3, 0);
    run_layer(c2W, c2D, 32,  64,  nullptr, 0,        catbs,      32);
    run_layer(c3W, c3D, 64,  128, nullptr, 32 * N3,  catbs,      96);
    run_layer(c4W, c4D, 128, 128, nullptr, 96 * N3,  catbs,      224);

    // cc layer
    {
        dim3 g(24, 16);
        size_t sm = (size_t)8 * CATC * sizeof(float);
        gemm_k<<<g, 128, sm>>>(ccW, 0, CATC, 0, nullptr, 0, CATC, catbs, 4, 128);
    }
    dc_k<<<48, 256>>>(ccD);
    ccact_k<<<BB * NN, 128>>>();
    reduce_k<<<BB * 128 * 3, 256>>>();

    head_k<<<BB, 128>>>(fcO, rbDin, rbW0, rbDh, rbW1, rbWs,
                        m0W, m0D, m1W, m1D, l0W, l0D, l1W, l1D,
                        fimW, filW, out);
}